// round 3
// baseline (speedup 1.0000x reference)
#include <cuda_runtime.h>
#include <cuda_bf16.h>

// Problem constants (fixed by setup_inputs):
//   x: [B=2, C=3, D=128, H=160, W=160] float32, num_steps = 6
#define BB    2
#define DD    128
#define HH    160
#define WW    160
#define PLANE (DD * HH * WW)          // 3,276,800 voxels per (batch) volume
#define NSTEPS 6

// Interleaved ping-pong scratch: float4 per voxel = (flow_d, flow_h, flow_w, 0).
// __device__ globals (allocation-free rule).
__device__ float4 g_bufA[BB * PLANE];
__device__ float4 g_bufB[BB * PLANE];

__device__ __forceinline__ int clampi(int v, int lo, int hi) {
    return min(max(v, lo), hi);
}

// ---------------------------------------------------------------------------
// Step 1: planar x -> interleaved. Scale fused (s = 1/2^6, exact pow2).
// Thread handles 4 consecutive W voxels (coalesced planar float4 reads).
// ---------------------------------------------------------------------------
__global__ __launch_bounds__(256) void sq_first(const float* __restrict__ x,
                                                float4* __restrict__ dst,
                                                float s) {
    const int W4 = WW / 4;
    int idx = blockIdx.x * blockDim.x + threadIdx.x;
    const int total = BB * DD * HH * W4;
    if (idx >= total) return;

    int w4 = idx % W4;
    int t  = idx / W4;
    int h  = t % HH;  t /= HH;
    int d  = t % DD;
    int b  = t / DD;

    const int p = (d * HH + h) * WW + w4 * 4;
    const float* __restrict__ sb = x + (size_t)b * 3 * PLANE;
    float4* __restrict__ db      = dst + (size_t)b * PLANE;

    float4 f0 = *reinterpret_cast<const float4*>(sb + p);              // d-flow
    float4 f1 = *reinterpret_cast<const float4*>(sb + p + PLANE);      // h-flow
    float4 f2 = *reinterpret_cast<const float4*>(sb + p + 2 * PLANE);  // w-flow

    f0.x *= s; f0.y *= s; f0.z *= s; f0.w *= s;
    f1.x *= s; f1.y *= s; f1.z *= s; f1.w *= s;
    f2.x *= s; f2.y *= s; f2.z *= s; f2.w *= s;

    float fd[4] = {f0.x, f0.y, f0.z, f0.w};
    float fh[4] = {f1.x, f1.y, f1.z, f1.w};
    float fw[4] = {f2.x, f2.y, f2.z, f2.w};

#pragma unroll
    for (int j = 0; j < 4; ++j) {
        int id = clampi(__float2int_rn((float)d + fd[j]), 0, DD - 1);
        int ih = clampi(__float2int_rn((float)h + fh[j]), 0, HH - 1);
        int iw = clampi(__float2int_rn((float)(w4 * 4 + j) + fw[j]), 0, WW - 1);
        const int q = (id * HH + ih) * WW + iw;
        float gd = s * sb[q];
        float gh = s * sb[q + PLANE];
        float gw = s * sb[q + 2 * PLANE];
        db[p + j] = make_float4(fd[j] + gd, fh[j] + gh, fw[j] + gw, 0.0f);
    }
}

// ---------------------------------------------------------------------------
// Steps 2..5: interleaved -> interleaved. 2 voxels/thread (2 in-flight gathers).
// ---------------------------------------------------------------------------
__global__ __launch_bounds__(256) void sq_mid(const float4* __restrict__ src,
                                              float4* __restrict__ dst) {
    int idx = blockIdx.x * blockDim.x + threadIdx.x;
    const int total = BB * PLANE / 2;
    if (idx >= total) return;

    int v = idx * 2;                   // even voxel index, pair never crosses row
    int b = v / PLANE;
    int r = v - b * PLANE;
    int w = r % WW;
    int t = r / WW;
    int h = t % HH;
    int d = t / HH;

    const float4* __restrict__ sb = src + (size_t)b * PLANE;
    float4* __restrict__ db       = dst + (size_t)b * PLANE;

    float4 a0 = sb[r];
    float4 a1 = sb[r + 1];

    int id0 = clampi(__float2int_rn((float)d + a0.x), 0, DD - 1);
    int ih0 = clampi(__float2int_rn((float)h + a0.y), 0, HH - 1);
    int iw0 = clampi(__float2int_rn((float)w + a0.z), 0, WW - 1);
    int id1 = clampi(__float2int_rn((float)d + a1.x), 0, DD - 1);
    int ih1 = clampi(__float2int_rn((float)h + a1.y), 0, HH - 1);
    int iw1 = clampi(__float2int_rn((float)(w + 1) + a1.z), 0, WW - 1);

    float4 g0 = sb[(id0 * HH + ih0) * WW + iw0];
    float4 g1 = sb[(id1 * HH + ih1) * WW + iw1];

    db[r]     = make_float4(a0.x + g0.x, a0.y + g0.y, a0.z + g0.z, 0.0f);
    db[r + 1] = make_float4(a1.x + g1.x, a1.y + g1.y, a1.z + g1.z, 0.0f);
}

// ---------------------------------------------------------------------------
// Step 6: interleaved -> planar d_out. 4 voxels/thread for coalesced planar
// float4 stores per channel.
// ---------------------------------------------------------------------------
__global__ __launch_bounds__(256) void sq_last(const float4* __restrict__ src,
                                               float* __restrict__ out) {
    const int W4 = WW / 4;
    int idx = blockIdx.x * blockDim.x + threadIdx.x;
    const int total = BB * DD * HH * W4;
    if (idx >= total) return;

    int w4 = idx % W4;
    int t  = idx / W4;
    int h  = t % HH;  t /= HH;
    int d  = t % DD;
    int b  = t / DD;

    const int p = (d * HH + h) * WW + w4 * 4;
    const float4* __restrict__ sb = src + (size_t)b * PLANE;
    float* __restrict__ ob        = out + (size_t)b * 3 * PLANE;

    float o0[4], o1[4], o2[4];
#pragma unroll
    for (int j = 0; j < 4; ++j) {
        float4 a = sb[p + j];
        int id = clampi(__float2int_rn((float)d + a.x), 0, DD - 1);
        int ih = clampi(__float2int_rn((float)h + a.y), 0, HH - 1);
        int iw = clampi(__float2int_rn((float)(w4 * 4 + j) + a.z), 0, WW - 1);
        float4 g = sb[(id * HH + ih) * WW + iw];
        o0[j] = a.x + g.x;
        o1[j] = a.y + g.y;
        o2[j] = a.z + g.z;
    }

    *reinterpret_cast<float4*>(ob + p)             = make_float4(o0[0], o0[1], o0[2], o0[3]);
    *reinterpret_cast<float4*>(ob + p + PLANE)     = make_float4(o1[0], o1[1], o1[2], o1[3]);
    *reinterpret_cast<float4*>(ob + p + 2 * PLANE) = make_float4(o2[0], o2[1], o2[2], o2[3]);
}

extern "C" void kernel_launch(void* const* d_in, const int* in_sizes, int n_in,
                              void* d_out, int out_size) {
    const float* x   = (const float*)d_in[0];
    float*       out = (float*)d_out;

    float4 *A = nullptr, *B = nullptr;
    cudaGetSymbolAddress((void**)&A, g_bufA);
    cudaGetSymbolAddress((void**)&B, g_bufB);

    const int tpb = 256;
    const int totQ = BB * DD * HH * (WW / 4);   // 4 voxels / thread kernels
    const int blkQ = (totQ + tpb - 1) / tpb;
    const int totM = BB * PLANE / 2;            // 2 voxels / thread kernels
    const int blkM = (totM + tpb - 1) / tpb;

    const float s0 = 1.0f / 64.0f;              // 1 / 2^num_steps (num_steps = 6)

    sq_first<<<blkQ, tpb>>>(x, A, s0);          // step 1: planar -> interleaved
    sq_mid  <<<blkM, tpb>>>(A, B);              // step 2
    sq_mid  <<<blkM, tpb>>>(B, A);              // step 3
    sq_mid  <<<blkM, tpb>>>(A, B);              // step 4
    sq_mid  <<<blkM, tpb>>>(B, A);              // step 5
    sq_last <<<blkQ, tpb>>>(A, out);            // step 6: interleaved -> planar
}

// round 6
// speedup vs baseline: 1.0965x; 1.0965x over previous
#include <cuda_runtime.h>
#include <cuda_bf16.h>

// Problem constants (fixed by setup_inputs):
//   x: [B=2, C=3, D=128, H=160, W=160] float32, num_steps = 6
#define BB    2
#define DD    128
#define HH    160
#define WW    160
#define PLANE (DD * HH * WW)          // 3,276,800 voxels per (batch) volume
#define NVOX  (BB * PLANE)            // 6,553,600 voxels total

// Interleaved ping-pong scratch: float4 per voxel = (flow_d, flow_h, flow_w, 0).
__device__ float4 g_bufA[NVOX];
__device__ float4 g_bufB[NVOX];

__device__ __forceinline__ int clampi(int v, int lo, int hi) {
    return min(max(v, lo), hi);
}

// ---------------------------------------------------------------------------
// Step 1: planar x -> interleaved. Scale fused (s = 1/2^6, exact pow2).
// Thread handles 4 consecutive W voxels (coalesced planar float4 reads).
// Gathers are near-identity at this step (|v0| ~ 0.125) so they coalesce.
// ---------------------------------------------------------------------------
__global__ __launch_bounds__(256) void sq_first(const float* __restrict__ x,
                                                float4* __restrict__ dst,
                                                float s) {
    const int W4 = WW / 4;
    int idx = blockIdx.x * blockDim.x + threadIdx.x;
    const int total = BB * DD * HH * W4;
    if (idx >= total) return;

    int w4 = idx % W4;
    int t  = idx / W4;
    int h  = t % HH;  t /= HH;
    int d  = t % DD;
    int b  = t / DD;

    const int p = (d * HH + h) * WW + w4 * 4;
    const float* __restrict__ sb = x + (size_t)b * 3 * PLANE;
    float4* __restrict__ db      = dst + (size_t)b * PLANE;

    float4 f0 = *reinterpret_cast<const float4*>(sb + p);              // d-flow
    float4 f1 = *reinterpret_cast<const float4*>(sb + p + PLANE);      // h-flow
    float4 f2 = *reinterpret_cast<const float4*>(sb + p + 2 * PLANE);  // w-flow

    f0.x *= s; f0.y *= s; f0.z *= s; f0.w *= s;
    f1.x *= s; f1.y *= s; f1.z *= s; f1.w *= s;
    f2.x *= s; f2.y *= s; f2.z *= s; f2.w *= s;

    float fd[4] = {f0.x, f0.y, f0.z, f0.w};
    float fh[4] = {f1.x, f1.y, f1.z, f1.w};
    float fw[4] = {f2.x, f2.y, f2.z, f2.w};

#pragma unroll
    for (int j = 0; j < 4; ++j) {
        int id = clampi(__float2int_rn((float)d + fd[j]), 0, DD - 1);
        int ih = clampi(__float2int_rn((float)h + fh[j]), 0, HH - 1);
        int iw = clampi(__float2int_rn((float)(w4 * 4 + j) + fw[j]), 0, WW - 1);
        const int q = (id * HH + ih) * WW + iw;
        float gd = s * sb[q];
        float gh = s * sb[q + PLANE];
        float gw = s * sb[q + 2 * PLANE];
        db[p + j] = make_float4(fd[j] + gd, fh[j] + gh, fw[j] + gw, 0.0f);
    }
}

// ---------------------------------------------------------------------------
// Steps 2..5: interleaved -> interleaved.
// 2 voxels/thread, WARP-CONTIGUOUS: v0 = base + lane, v1 = v0 + 32.
// Stream loads/stores fully coalesced; 2 independent gathers in flight.
// NVOX = 6,553,600 = 12800 blocks * 512 voxels exactly.
// ---------------------------------------------------------------------------
__global__ __launch_bounds__(256) void sq_mid(const float4* __restrict__ src,
                                              float4* __restrict__ dst) {
    const int lane = threadIdx.x & 31;
    const int warp = threadIdx.x >> 5;
    const int v0 = blockIdx.x * 512 + warp * 64 + lane;   // in [0, NVOX)
    const int v1 = v0 + 32;

    float4 a0 = src[v0];
    float4 a1 = src[v1];

    // decode (b, d, h, w) for both voxels
    int b0 = v0 / PLANE, r0 = v0 - b0 * PLANE;
    int w0 = r0 % WW;  int t0 = r0 / WW;
    int h0 = t0 % HH;  int d0 = t0 / HH;

    int b1 = v1 / PLANE, r1 = v1 - b1 * PLANE;
    int w1 = r1 % WW;  int t1 = r1 / WW;
    int h1 = t1 % HH;  int d1 = t1 / HH;

    int id0 = clampi(__float2int_rn((float)d0 + a0.x), 0, DD - 1);
    int ih0 = clampi(__float2int_rn((float)h0 + a0.y), 0, HH - 1);
    int iw0 = clampi(__float2int_rn((float)w0 + a0.z), 0, WW - 1);
    int id1 = clampi(__float2int_rn((float)d1 + a1.x), 0, DD - 1);
    int ih1 = clampi(__float2int_rn((float)h1 + a1.y), 0, HH - 1);
    int iw1 = clampi(__float2int_rn((float)w1 + a1.z), 0, WW - 1);

    const float4* __restrict__ sb0 = src + (size_t)b0 * PLANE;
    const float4* __restrict__ sb1 = src + (size_t)b1 * PLANE;
    float4 g0 = sb0[(id0 * HH + ih0) * WW + iw0];
    float4 g1 = sb1[(id1 * HH + ih1) * WW + iw1];

    dst[v0] = make_float4(a0.x + g0.x, a0.y + g0.y, a0.z + g0.z, 0.0f);
    dst[v1] = make_float4(a1.x + g1.x, a1.y + g1.y, a1.z + g1.z, 0.0f);
}

// ---------------------------------------------------------------------------
// Step 6: interleaved -> planar d_out. 4 voxels/thread for coalesced planar
// float4 stores per channel.
// ---------------------------------------------------------------------------
__global__ __launch_bounds__(256) void sq_last(const float4* __restrict__ src,
                                               float* __restrict__ out) {
    const int W4 = WW / 4;
    int idx = blockIdx.x * blockDim.x + threadIdx.x;
    const int total = BB * DD * HH * W4;
    if (idx >= total) return;

    int w4 = idx % W4;
    int t  = idx / W4;
    int h  = t % HH;  t /= HH;
    int d  = t % DD;
    int b  = t / DD;

    const int p = (d * HH + h) * WW + w4 * 4;
    const float4* __restrict__ sb = src + (size_t)b * PLANE;
    float* __restrict__ ob        = out + (size_t)b * 3 * PLANE;

    float o0[4], o1[4], o2[4];
#pragma unroll
    for (int j = 0; j < 4; ++j) {
        float4 a = sb[p + j];
        int id = clampi(__float2int_rn((float)d + a.x), 0, DD - 1);
        int ih = clampi(__float2int_rn((float)h + a.y), 0, HH - 1);
        int iw = clampi(__float2int_rn((float)(w4 * 4 + j) + a.z), 0, WW - 1);
        float4 g = sb[(id * HH + ih) * WW + iw];
        o0[j] = a.x + g.x;
        o1[j] = a.y + g.y;
        o2[j] = a.z + g.z;
    }

    *reinterpret_cast<float4*>(ob + p)             = make_float4(o0[0], o0[1], o0[2], o0[3]);
    *reinterpret_cast<float4*>(ob + p + PLANE)     = make_float4(o1[0], o1[1], o1[2], o1[3]);
    *reinterpret_cast<float4*>(ob + p + 2 * PLANE) = make_float4(o2[0], o2[1], o2[2], o2[3]);
}

extern "C" void kernel_launch(void* const* d_in, const int* in_sizes, int n_in,
                              void* d_out, int out_size) {
    const float* x   = (const float*)d_in[0];
    float*       out = (float*)d_out;

    float4 *A = nullptr, *B = nullptr;
    cudaGetSymbolAddress((void**)&A, g_bufA);
    cudaGetSymbolAddress((void**)&B, g_bufB);

    const int tpb  = 256;
    const int totQ = BB * DD * HH * (WW / 4);   // 4 voxels / thread kernels
    const int blkQ = (totQ + tpb - 1) / tpb;
    const int blkM = NVOX / 512;                // 12800, exact

    const float s0 = 1.0f / 64.0f;              // 1 / 2^num_steps (num_steps = 6)

    sq_first<<<blkQ, tpb>>>(x, A, s0);          // step 1: planar -> interleaved
    sq_mid  <<<blkM, tpb>>>(A, B);              // step 2
    sq_mid  <<<blkM, tpb>>>(B, A);              // step 3
    sq_mid  <<<blkM, tpb>>>(A, B);              // step 4
    sq_mid  <<<blkM, tpb>>>(B, A);              // step 5
    sq_last <<<blkQ, tpb>>>(A, out);            // step 6: interleaved -> planar
}

// round 7
// speedup vs baseline: 1.1276x; 1.0284x over previous
#include <cuda_runtime.h>
#include <cuda_bf16.h>

// Problem constants (fixed by setup_inputs):
//   x: [B=2, C=3, D=128, H=160, W=160] float32, num_steps = 6
#define BB    2
#define DD    128
#define HH    160
#define WW    160
#define PLANE (DD * HH * WW)          // 3,276,800 voxels per (batch) volume
#define NVOX  (BB * PLANE)

// Interleaved ping-pong scratch: float4 per voxel = (flow_d, flow_h, flow_w, 0).
// Per-batch halves are processed sequentially so the active working set
// (2 x 52.4 MB) stays L2-resident (126 MB).
__device__ float4 g_bufA[NVOX];
__device__ float4 g_bufB[NVOX];

__device__ __forceinline__ int clampi(int v, int lo, int hi) {
    return min(max(v, lo), hi);
}

// ---------------------------------------------------------------------------
// Step 1 (one batch): planar x -> interleaved. Scale fused (s = 1/64, pow2).
// Thread handles 4 consecutive W voxels (coalesced planar float4 reads).
// ---------------------------------------------------------------------------
__global__ __launch_bounds__(256) void sq_first(const float* __restrict__ sb,
                                                float4* __restrict__ db,
                                                float s) {
    const int W4 = WW / 4;
    int idx = blockIdx.x * blockDim.x + threadIdx.x;   // grid covers DD*HH*W4
    int w4 = idx % W4;
    int t  = idx / W4;
    int h  = t % HH;
    int d  = t / HH;

    const int p = (d * HH + h) * WW + w4 * 4;

    float4 f0 = *reinterpret_cast<const float4*>(sb + p);              // d-flow
    float4 f1 = *reinterpret_cast<const float4*>(sb + p + PLANE);      // h-flow
    float4 f2 = *reinterpret_cast<const float4*>(sb + p + 2 * PLANE);  // w-flow

    f0.x *= s; f0.y *= s; f0.z *= s; f0.w *= s;
    f1.x *= s; f1.y *= s; f1.z *= s; f1.w *= s;
    f2.x *= s; f2.y *= s; f2.z *= s; f2.w *= s;

    float fd[4] = {f0.x, f0.y, f0.z, f0.w};
    float fh[4] = {f1.x, f1.y, f1.z, f1.w};
    float fw[4] = {f2.x, f2.y, f2.z, f2.w};

#pragma unroll
    for (int j = 0; j < 4; ++j) {
        int id = clampi(__float2int_rn((float)d + fd[j]), 0, DD - 1);
        int ih = clampi(__float2int_rn((float)h + fh[j]), 0, HH - 1);
        int iw = clampi(__float2int_rn((float)(w4 * 4 + j) + fw[j]), 0, WW - 1);
        const int q = (id * HH + ih) * WW + iw;
        float gd = s * sb[q];
        float gh = s * sb[q + PLANE];
        float gw = s * sb[q + 2 * PLANE];
        db[p + j] = make_float4(fd[j] + gd, fh[j] + gh, fw[j] + gw, 0.0f);
    }
}

// ---------------------------------------------------------------------------
// Steps 2..5 (one batch): interleaved -> interleaved.
// 2 voxels/thread, warp-contiguous: v0 = base + lane, v1 = v0 + 32.
// PLANE = 3,276,800 = 6400 blocks * 512 voxels exactly.
// ---------------------------------------------------------------------------
__global__ __launch_bounds__(256) void sq_mid(const float4* __restrict__ src,
                                              float4* __restrict__ dst) {
    const int lane = threadIdx.x & 31;
    const int warp = threadIdx.x >> 5;
    const int v0 = blockIdx.x * 512 + warp * 64 + lane;   // in [0, PLANE)
    const int v1 = v0 + 32;

    float4 a0 = src[v0];
    float4 a1 = src[v1];

    int w0 = v0 % WW;  int t0 = v0 / WW;
    int h0 = t0 % HH;  int d0 = t0 / HH;
    int w1 = v1 % WW;  int t1 = v1 / WW;
    int h1 = t1 % HH;  int d1 = t1 / HH;

    int id0 = clampi(__float2int_rn((float)d0 + a0.x), 0, DD - 1);
    int ih0 = clampi(__float2int_rn((float)h0 + a0.y), 0, HH - 1);
    int iw0 = clampi(__float2int_rn((float)w0 + a0.z), 0, WW - 1);
    int id1 = clampi(__float2int_rn((float)d1 + a1.x), 0, DD - 1);
    int ih1 = clampi(__float2int_rn((float)h1 + a1.y), 0, HH - 1);
    int iw1 = clampi(__float2int_rn((float)w1 + a1.z), 0, WW - 1);

    float4 g0 = src[(id0 * HH + ih0) * WW + iw0];
    float4 g1 = src[(id1 * HH + ih1) * WW + iw1];

    dst[v0] = make_float4(a0.x + g0.x, a0.y + g0.y, a0.z + g0.z, 0.0f);
    dst[v1] = make_float4(a1.x + g1.x, a1.y + g1.y, a1.z + g1.z, 0.0f);
}

// ---------------------------------------------------------------------------
// Step 6 (one batch): interleaved -> planar out. 4 voxels/thread, coalesced
// planar float4 stores per channel.
// ---------------------------------------------------------------------------
__global__ __launch_bounds__(256) void sq_last(const float4* __restrict__ sb,
                                               float* __restrict__ ob) {
    const int W4 = WW / 4;
    int idx = blockIdx.x * blockDim.x + threadIdx.x;
    int w4 = idx % W4;
    int t  = idx / W4;
    int h  = t % HH;
    int d  = t / HH;

    const int p = (d * HH + h) * WW + w4 * 4;

    float o0[4], o1[4], o2[4];
#pragma unroll
    for (int j = 0; j < 4; ++j) {
        float4 a = sb[p + j];
        int id = clampi(__float2int_rn((float)d + a.x), 0, DD - 1);
        int ih = clampi(__float2int_rn((float)h + a.y), 0, HH - 1);
        int iw = clampi(__float2int_rn((float)(w4 * 4 + j) + a.z), 0, WW - 1);
        float4 g = sb[(id * HH + ih) * WW + iw];
        o0[j] = a.x + g.x;
        o1[j] = a.y + g.y;
        o2[j] = a.z + g.z;
    }

    *reinterpret_cast<float4*>(ob + p)             = make_float4(o0[0], o0[1], o0[2], o0[3]);
    *reinterpret_cast<float4*>(ob + p + PLANE)     = make_float4(o1[0], o1[1], o1[2], o1[3]);
    *reinterpret_cast<float4*>(ob + p + 2 * PLANE) = make_float4(o2[0], o2[1], o2[2], o2[3]);
}

extern "C" void kernel_launch(void* const* d_in, const int* in_sizes, int n_in,
                              void* d_out, int out_size) {
    const float* x   = (const float*)d_in[0];
    float*       out = (float*)d_out;

    float4 *A = nullptr, *B = nullptr;
    cudaGetSymbolAddress((void**)&A, g_bufA);
    cudaGetSymbolAddress((void**)&B, g_bufB);

    const int tpb  = 256;
    const int blkQ = (DD * HH * (WW / 4)) / tpb;   // 320 * 40 = 12800 threads... = 320 blocks
    const int blkM = PLANE / 512;                  // 6400, exact

    const float s0 = 1.0f / 64.0f;                 // 1 / 2^num_steps (num_steps = 6)

    // Process each batch sample fully before the next: keeps the per-batch
    // ping-pong working set (105 MB) resident in the 126 MB L2.
    for (int b = 0; b < BB; ++b) {
        const float* xb = x   + (size_t)b * 3 * PLANE;
        float*       ob = out + (size_t)b * 3 * PLANE;
        float4*      Ab = A   + (size_t)b * PLANE;
        float4*      Bb = B   + (size_t)b * PLANE;

        sq_first<<<blkQ, tpb>>>(xb, Ab, s0);   // step 1: planar -> interleaved
        sq_mid  <<<blkM, tpb>>>(Ab, Bb);       // step 2
        sq_mid  <<<blkM, tpb>>>(Bb, Ab);       // step 3
        sq_mid  <<<blkM, tpb>>>(Ab, Bb);       // step 4
        sq_mid  <<<blkM, tpb>>>(Bb, Ab);       // step 5
        sq_last <<<blkQ, tpb>>>(Ab, ob);       // step 6: interleaved -> planar
    }
}